// round 1
// baseline (speedup 1.0000x reference)
#include <cuda_runtime.h>
#include <math.h>

#define B_   128
#define N_   8
#define LQ   32
#define LD   256
#define D_   128
#define RT   64          // rows per chunk
#define NEGV (-9999.0f)

// persistent scratch (no allocs allowed)
__device__ float g_qT[B_ * D_ * LQ];        // [b][k][j]  (transposed, normalized q)
__device__ float g_scores[2 * N_ * B_];     // [z][n][b]  z=0 student(cq), z=1 teacher(orig)

// ---------------------------------------------------------------------------
// Kernel 1: normalize q rows, store transposed per-b:  g_qT[b][k][j]
// one warp per (b, j)
// ---------------------------------------------------------------------------
__global__ void __launch_bounds__(128) qnorm_kernel(const float* __restrict__ q)
{
    int gw   = blockIdx.x * (blockDim.x >> 5) + (threadIdx.x >> 5);
    int lane = threadIdx.x & 31;
    if (gw >= B_ * LQ) return;
    int b = gw >> 5;
    int j = gw & 31;

    const float4* row = (const float4*)(q + (size_t)gw * D_);
    float4 v = row[lane];
    float ss = v.x * v.x + v.y * v.y + v.z * v.z + v.w * v.w;
#pragma unroll
    for (int o = 16; o; o >>= 1) ss += __shfl_xor_sync(0xffffffffu, ss, o);
    float inv = 1.0f / fmaxf(sqrtf(ss), 1e-12f);

    float* dst = g_qT + (size_t)b * (D_ * LQ);
    int k = lane * 4;
    dst[(k + 0) * LQ + j] = v.x * inv;
    dst[(k + 1) * LQ + j] = v.y * inv;
    dst[(k + 2) * LQ + j] = v.z * inv;
    dst[(k + 3) * LQ + j] = v.w * inv;
}

// ---------------------------------------------------------------------------
// Kernel 2: MaxSim. grid = (B, N, 2); 256 threads.
// Per CTA: compact active rows, then chunks of 64 rows:
//   load rows -> swizzled transposed smem tile (two 64-wide K halves),
//   2q x 4r register-tile FP32 GEMM, scale by 1/||d||, running max.
// ---------------------------------------------------------------------------
__global__ void __launch_bounds__(256) maxsim_kernel(const float* __restrict__ dcq,
                                                     const float* __restrict__ dorig,
                                                     const int*   __restrict__ mask)
{
    __shared__ float  sQ[D_ * LQ];        // 16 KB  qT[k][j]
    __shared__ float4 sD4[64 * 16];       // 16 KB  swizzled dT: 64 k x 64 rows
    __shared__ float  sSS[RT];            // sum of squares per row
    __shared__ float  sBias[RT];          // 0 valid, -1e30 pad
    __shared__ float  sQmax[LQ];
    __shared__ int    sAct[LD];
    __shared__ int    sCnt;

    const int b = blockIdx.x, n = blockIdx.y, z = blockIdx.z;
    const int t = threadIdx.x;
    const float* __restrict__ dbase = z ? dorig : dcq;
    const int    pair  = n * B_ + b;
    const float* __restrict__ dpair = dbase + (size_t)pair * (LD * D_);

    // ---- q tile (already normalized + transposed) ----
    const float* qsrc = g_qT + (size_t)b * (D_ * LQ);
#pragma unroll
    for (int i = 0; i < 16; i++) sQ[i * 256 + t] = qsrc[i * 256 + t];
    if (t == 0) sCnt = 0;
    __syncthreads();

    // ---- mask compaction (order irrelevant: max is commutative) ----
    if (mask[pair * LD + t]) {
        int p = atomicAdd(&sCnt, 1);
        sAct[p] = t;
    }
    __syncthreads();
    const int cnt = sCnt;

    const int rg = t & 15;    // row group: rows 4rg..4rg+3
    const int qg = t >> 4;    // query group: queries 2qg, 2qg+1
    float mx0 = NEGV, mx1 = NEGV;

    const int nch = (cnt + RT - 1) >> 6;
    for (int ch = 0; ch < nch; ch++) {
        float a0[4] = {0.f, 0.f, 0.f, 0.f};
        float a1[4] = {0.f, 0.f, 0.f, 0.f};

#pragma unroll
        for (int half = 0; half < 2; half++) {
            __syncthreads();   // protect sD4/sSS/sBias from previous readers
            // ---- load 64 rows x 64 floats, transpose into swizzled smem ----
#pragma unroll
            for (int it = 0; it < 4; it++) {
                int li = it * 256 + t;
                int rl = li >> 4;          // 0..63  local row
                int k4 = li & 15;          // float4 index along k (this half)
                int i  = ch * RT + rl;
                bool valid = (i < cnt);
                float4 v = make_float4(0.f, 0.f, 0.f, 0.f);
                if (valid) {
                    int rowg = sAct[i];
                    v = *(const float4*)(dpair + rowg * D_ + half * 64 + k4 * 4);
                }
                float ss = v.x * v.x + v.y * v.y + v.z * v.z + v.w * v.w;
#pragma unroll
                for (int o = 8; o; o >>= 1) ss += __shfl_xor_sync(0xffffffffu, ss, o, 16);
                if ((t & 15) == 0) {
                    if (half == 0) { sSS[rl] = ss; sBias[rl] = valid ? 0.0f : -1e30f; }
                    else           { sSS[rl] += ss; }
                }
                // swizzle: float4-col = ((rl>>2) + k4) & 15  -> conflict-free STS,
                //          2-phase LDS.128 on the GEMM side
                int col = ((rl >> 2) + k4) & 15;
                float* dst = (float*)sD4 + (k4 * 4) * 64 + col * 4 + (rl & 3);
                dst[0]   = v.x;
                dst[64]  = v.y;
                dst[128] = v.z;
                dst[192] = v.w;
            }
            __syncthreads();

            // ---- GEMM over this 64-wide K half ----
            const float* sQh = sQ + half * 64 * LQ;
#pragma unroll 8
            for (int k = 0; k < 64; k++) {
                float2 qv = *(const float2*)(sQh + k * LQ + 2 * qg);
                float4 dv = sD4[k * 16 + ((rg + (k >> 2)) & 15)];
                a0[0] = fmaf(qv.x, dv.x, a0[0]);
                a0[1] = fmaf(qv.x, dv.y, a0[1]);
                a0[2] = fmaf(qv.x, dv.z, a0[2]);
                a0[3] = fmaf(qv.x, dv.w, a0[3]);
                a1[0] = fmaf(qv.y, dv.x, a1[0]);
                a1[1] = fmaf(qv.y, dv.y, a1[1]);
                a1[2] = fmaf(qv.y, dv.z, a1[2]);
                a1[3] = fmaf(qv.y, dv.w, a1[3]);
            }
        }

        // ---- scale by 1/||d|| and fold into running max ----
#pragma unroll
        for (int rr = 0; rr < 4; rr++) {
            int r = 4 * rg + rr;
            float inv  = 1.0f / fmaxf(sqrtf(sSS[r]), 1e-12f);
            float bias = sBias[r];
            mx0 = fmaxf(mx0, fmaf(a0[rr], inv, bias));
            mx1 = fmaxf(mx1, fmaf(a1[rr], inv, bias));
        }
    }

    // ---- max over the 16 row-groups sharing each query (16-lane segments) ----
#pragma unroll
    for (int o = 8; o; o >>= 1) {
        mx0 = fmaxf(mx0, __shfl_down_sync(0xffffffffu, mx0, o, 16));
        mx1 = fmaxf(mx1, __shfl_down_sync(0xffffffffu, mx1, o, 16));
    }
    if (rg == 0) { sQmax[2 * qg] = mx0; sQmax[2 * qg + 1] = mx1; }
    __syncthreads();

    // ---- sum over the 32 query maxima ----
    if (t < 32) {
        float v = sQmax[t];
#pragma unroll
        for (int o = 16; o; o >>= 1) v += __shfl_xor_sync(0xffffffffu, v, o);
        if (t == 0) g_scores[(z * N_ + n) * B_ + b] = v;
    }
}

// ---------------------------------------------------------------------------
// Kernel 3: KL(batchmean) over [B, N] score matrices
// ---------------------------------------------------------------------------
__global__ void __launch_bounds__(128) loss_kernel(float* __restrict__ out)
{
    int b = threadIdx.x;
    float s[N_], tt[N_];
#pragma unroll
    for (int n = 0; n < N_; n++) {
        s[n]  = g_scores[n * B_ + b];
        tt[n] = g_scores[(N_ + n) * B_ + b];
    }
    float ms = s[0], mt = tt[0];
#pragma unroll
    for (int n = 1; n < N_; n++) { ms = fmaxf(ms, s[n]); mt = fmaxf(mt, tt[n]); }
    float es = 0.f, et = 0.f;
#pragma unroll
    for (int n = 0; n < N_; n++) { es += expf(s[n] - ms); et += expf(tt[n] - mt); }
    float lses = ms + logf(es);
    float lset = mt + logf(et);
    float kl = 0.f;
#pragma unroll
    for (int n = 0; n < N_; n++) {
        float lt = tt[n] - lset;
        float ls = s[n]  - lses;
        kl += expf(lt) * (lt - ls);
    }
    __shared__ float red[128];
    red[b] = kl;
    __syncthreads();
#pragma unroll
    for (int o = 64; o; o >>= 1) {
        if (b < o) red[b] += red[b + o];
        __syncthreads();
    }
    if (b == 0) out[0] = red[0] / (float)B_;
}

// ---------------------------------------------------------------------------
extern "C" void kernel_launch(void* const* d_in, const int* in_sizes, int n_in,
                              void* d_out, int out_size)
{
    const float* q     = (const float*)d_in[0];   // [B,Lq,D]
    const float* dcq   = (const float*)d_in[1];   // [N,B,Ld,D]
    const float* dorig = (const float*)d_in[2];   // [N,B,Ld,D]
    const int*   mask  = (const int*)d_in[3];     // [N,B,Ld]
    // d_in[4] = labels (unused by the reference loss path)

    qnorm_kernel<<<(B_ * LQ) / 4, 128>>>(q);
    dim3 grid(B_, N_, 2);
    maxsim_kernel<<<grid, 256>>>(dcq, dorig, mask);
    loss_kernel<<<1, 128>>>((float*)d_out);
}